// round 3
// baseline (speedup 1.0000x reference)
#include <cuda_runtime.h>

#define B_ 4
#define C_ 64
#define N_ 6400
#define NTILES 100   // N_/64

// ---------------- scratch (device globals; no allocation allowed) ----------
__device__ float g_theta[B_*C_*N_];   // [B][C][N]
__device__ float g_phi  [B_*C_*N_];   // [B][C][N]
__device__ float g_gv   [B_*C_*N_];   // [B][C][N]
__device__ float g_y    [B_*C_*N_];   // [B][C][N]
__device__ float g_Wy   [B_*C_*N_];   // [B][C][N]
__device__ float g_stats[2*C_];       // per-channel sum, sumsq
__device__ float g_sc   [2*C_];       // per-channel scale, shift

// ---------------- f32x2 packed-math helpers (sm_100+) ----------------------
__device__ __forceinline__ unsigned long long pk2(float lo, float hi) {
    unsigned long long r;
    asm("mov.b64 %0, {%1, %2};" : "=l"(r)
        : "r"(__float_as_uint(lo)), "r"(__float_as_uint(hi)));
    return r;
}
__device__ __forceinline__ void upk2(unsigned long long v, float &lo, float &hi) {
    unsigned int a, b;
    asm("mov.b64 {%0, %1}, %2;" : "=r"(a), "=r"(b) : "l"(v));
    lo = __uint_as_float(a);
    hi = __uint_as_float(b);
}
__device__ __forceinline__ void fma2(unsigned long long &d,
                                     unsigned long long a, unsigned long long b) {
    asm("fma.rn.f32x2 %0, %1, %2, %0;" : "+l"(d) : "l"(a), "l"(b));
}
__device__ __forceinline__ void mul2(unsigned long long &d, unsigned long long a) {
    asm("mul.rn.f32x2 %0, %1, %0;" : "+l"(d) : "l"(a));
}

// ---------------- kernel 1: fused theta/phi/g projections ------------------
// out[b][o][n] = sum_c x[b][c][n] * w[o][c] + bias[o], for 3 weight sets.
__global__ __launch_bounds__(256) void proj3_kernel(
    const float* __restrict__ x,
    const float* __restrict__ wt, const float* __restrict__ bt,
    const float* __restrict__ wp, const float* __restrict__ bp,
    const float* __restrict__ wg, const float* __restrict__ bg)
{
    __shared__ __align__(16) float xs[64*68];  // xs[c][n]
    __shared__ __align__(16) float ws[64*68];  // ws[c][o] (transposed weights)
    const int b  = blockIdx.y;
    const int n0 = blockIdx.x * 64;
    const int t  = threadIdx.x;
    const int tx = t & 15, ty = t >> 4;

    // zero the BN stats accumulator once per launch (stream-ordered before convW)
    if (blockIdx.x == 0 && b == 0 && t < 128) g_stats[t] = 0.f;

    for (int i = t; i < 4096; i += 256) {
        int c = i >> 6, n = i & 63;
        xs[c*68 + n] = x[((size_t)b*64 + c)*6400 + n0 + n];
    }

    const float* W[3]  = {wt, wp, wg};
    const float* BV[3] = {bt, bp, bg};
    float* OUT[3]      = {g_theta, g_phi, g_gv};

    for (int m = 0; m < 3; m++) {
        __syncthreads();   // first iter: xs done; later: ws reads done
        for (int i = t; i < 4096; i += 256) {
            int o = i >> 6, c = i & 63;
            ws[c*68 + o] = W[m][i];
        }
        __syncthreads();

        float acc[4][4];
        #pragma unroll
        for (int j = 0; j < 4; j++) {
            float bb = BV[m][4*tx + j];
            #pragma unroll
            for (int r = 0; r < 4; r++) acc[r][j] = bb;
        }
        #pragma unroll 4
        for (int c = 0; c < 64; c++) {
            float4 a  = *(const float4*)&xs[c*68 + 4*ty];
            float4 w4 = *(const float4*)&ws[c*68 + 4*tx];
            acc[0][0] += a.x*w4.x; acc[0][1] += a.x*w4.y; acc[0][2] += a.x*w4.z; acc[0][3] += a.x*w4.w;
            acc[1][0] += a.y*w4.x; acc[1][1] += a.y*w4.y; acc[1][2] += a.y*w4.z; acc[1][3] += a.y*w4.w;
            acc[2][0] += a.z*w4.x; acc[2][1] += a.z*w4.y; acc[2][2] += a.z*w4.z; acc[2][3] += a.z*w4.w;
            acc[3][0] += a.w*w4.x; acc[3][1] += a.w*w4.y; acc[3][2] += a.w*w4.z; acc[3][3] += a.w*w4.w;
        }
        float* dst = OUT[m] + (size_t)b*64*6400;
        #pragma unroll
        for (int j = 0; j < 4; j++) {
            float4 v = make_float4(acc[0][j], acc[1][j], acc[2][j], acc[3][j]);
            *(float4*)&dst[(4*tx + j)*6400 + n0 + 4*ty] = v;
        }
    }
}

// ---------------- kernel 2: fused flash attention (fp32, f32x2 FMA) --------
__global__ __launch_bounds__(256, 3) void flash_kernel()
{
    __shared__ __align__(16) float Qt[64*64];  // Qt[c][n]
    __shared__ __align__(16) float KP[64*64];  // K[c][m], later P[n][m]
    __shared__ __align__(16) float Vs[64*64];  // V[m][c] xor-swizzled

    const int b  = blockIdx.y;
    const int n0 = blockIdx.x * 64;
    const int t  = threadIdx.x;
    const int tx = t & 15, ty = t >> 4;

    const float* th = g_theta + (size_t)b*64*6400;
    const float* ph = g_phi   + (size_t)b*64*6400;
    const float* gv = g_gv    + (size_t)b*64*6400;

    for (int i = t; i < 4096; i += 256) {
        int c = i >> 6, n = i & 63;
        Qt[c*64 + n] = th[c*6400 + n0 + n];
    }

    unsigned long long O2[4][2];
    #pragma unroll
    for (int r = 0; r < 4; r++) { O2[r][0] = 0ull; O2[r][1] = 0ull; }
    float mi[4], li[4];
    #pragma unroll
    for (int r = 0; r < 4; r++) { mi[r] = -1e30f; li[r] = 0.f; }

    for (int m0 = 0; m0 < 6400; m0 += 64) {
        __syncthreads();   // previous PV reads of KP/Vs complete
        for (int i = t; i < 4096; i += 256) {
            int c = i >> 6, mm = i & 63;
            float kv = ph[c*6400 + m0 + mm];
            float vv = gv[c*6400 + m0 + mm];
            KP[c*64 + mm] = kv;
            Vs[mm*64 + (c ^ ((mm & 15) << 2))] = vv;   // transpose+swizzle
        }
        __syncthreads();

        // --- S = Q Kᵀ (rank-1 updates over c, packed f32x2) ---
        unsigned long long S2[4][2];
        #pragma unroll
        for (int r = 0; r < 4; r++) { S2[r][0] = 0ull; S2[r][1] = 0ull; }
        #pragma unroll 4
        for (int c = 0; c < 64; c++) {
            ulonglong2 bq = *(const ulonglong2*)&KP[c*64 + 4*tx];
            float4 av = *(const float4*)&Qt[c*64 + 4*ty];
            unsigned long long a0 = pk2(av.x, av.x);
            unsigned long long a1 = pk2(av.y, av.y);
            unsigned long long a2 = pk2(av.z, av.z);
            unsigned long long a3 = pk2(av.w, av.w);
            fma2(S2[0][0], a0, bq.x); fma2(S2[0][1], a0, bq.y);
            fma2(S2[1][0], a1, bq.x); fma2(S2[1][1], a1, bq.y);
            fma2(S2[2][0], a2, bq.x); fma2(S2[2][1], a2, bq.y);
            fma2(S2[3][0], a3, bq.x); fma2(S2[3][1], a3, bq.y);
        }

        // --- online softmax (rows owned by 16-lane tx groups) ---
        float S[4][4], P[4][4];
        #pragma unroll
        for (int r = 0; r < 4; r++) {
            upk2(S2[r][0], S[r][0], S[r][1]);
            upk2(S2[r][1], S[r][2], S[r][3]);
        }
        #pragma unroll
        for (int r = 0; r < 4; r++) {
            float mx = fmaxf(fmaxf(S[r][0], S[r][1]), fmaxf(S[r][2], S[r][3]));
            #pragma unroll
            for (int o = 1; o < 16; o <<= 1)
                mx = fmaxf(mx, __shfl_xor_sync(0xffffffffu, mx, o));
            float mn = fmaxf(mi[r], mx);
            float s = 0.f;
            #pragma unroll
            for (int j = 0; j < 4; j++) {
                P[r][j] = __expf(S[r][j] - mn);
                s += P[r][j];
            }
            #pragma unroll
            for (int o = 1; o < 16; o <<= 1)
                s += __shfl_xor_sync(0xffffffffu, s, o);
            float alpha = __expf(mi[r] - mn);
            li[r] = li[r]*alpha + s;
            mi[r] = mn;
            unsigned long long ad = pk2(alpha, alpha);
            mul2(O2[r][0], ad);
            mul2(O2[r][1], ad);
        }

        __syncthreads();   // all S-GEMM reads of K done before P overwrite
        #pragma unroll
        for (int r = 0; r < 4; r++)
            *(float4*)&KP[(4*ty + r)*64 + 4*tx] =
                make_float4(P[r][0], P[r][1], P[r][2], P[r][3]);
        __syncthreads();

        // --- O += P V (rank-1 over m, packed f32x2) ---
        #pragma unroll 4
        for (int k = 0; k < 64; k++) {
            ulonglong2 bv = *(const ulonglong2*)&Vs[k*64 + ((4*tx) ^ ((k & 15) << 2))];
            #pragma unroll
            for (int r = 0; r < 4; r++) {
                float p = KP[(4*ty + r)*64 + k];
                unsigned long long ap = pk2(p, p);
                fma2(O2[r][0], ap, bv.x);
                fma2(O2[r][1], ap, bv.y);
            }
        }
    }

    // --- epilogue: normalize and write y[b][c][n] ---
    float Of[4][4];
    #pragma unroll
    for (int r = 0; r < 4; r++) {
        upk2(O2[r][0], Of[r][0], Of[r][1]);
        upk2(O2[r][1], Of[r][2], Of[r][3]);
        float inv = 1.f / li[r];
        #pragma unroll
        for (int j = 0; j < 4; j++) Of[r][j] *= inv;
    }
    float* y = g_y + (size_t)b*64*6400;
    #pragma unroll
    for (int j = 0; j < 4; j++) {
        float4 v = make_float4(Of[0][j], Of[1][j], Of[2][j], Of[3][j]);
        *(float4*)&y[(4*tx + j)*6400 + n0 + 4*ty] = v;
    }
}

// ---------------- kernel 3: W-conv + BN statistics --------------------------
__global__ __launch_bounds__(256) void convW_kernel(
    const float* __restrict__ wW, const float* __restrict__ bW)
{
    __shared__ __align__(16) float ys[64*68];  // ys[c][n]
    __shared__ __align__(16) float ws[64*68];  // ws[c][o]
    __shared__ float ssum[64], ssq[64];
    const int b  = blockIdx.y;
    const int n0 = blockIdx.x * 64;
    const int t  = threadIdx.x;
    const int tx = t & 15, ty = t >> 4;

    const float* yb = g_y + (size_t)b*64*6400;
    for (int i = t; i < 4096; i += 256) {
        int c = i >> 6, n = i & 63;
        ys[c*68 + n] = yb[c*6400 + n0 + n];
    }
    for (int i = t; i < 4096; i += 256) {
        int o = i >> 6, c = i & 63;
        ws[c*68 + o] = wW[i];
    }
    if (t < 64) { ssum[t] = 0.f; ssq[t] = 0.f; }
    __syncthreads();

    float acc[4][4];
    #pragma unroll
    for (int j = 0; j < 4; j++) {
        float bb = bW[4*tx + j];
        #pragma unroll
        for (int r = 0; r < 4; r++) acc[r][j] = bb;
    }
    #pragma unroll 4
    for (int c = 0; c < 64; c++) {
        float4 a  = *(const float4*)&ys[c*68 + 4*ty];
        float4 w4 = *(const float4*)&ws[c*68 + 4*tx];
        acc[0][0] += a.x*w4.x; acc[0][1] += a.x*w4.y; acc[0][2] += a.x*w4.z; acc[0][3] += a.x*w4.w;
        acc[1][0] += a.y*w4.x; acc[1][1] += a.y*w4.y; acc[1][2] += a.y*w4.z; acc[1][3] += a.y*w4.w;
        acc[2][0] += a.z*w4.x; acc[2][1] += a.z*w4.y; acc[2][2] += a.z*w4.z; acc[2][3] += a.z*w4.w;
        acc[3][0] += a.w*w4.x; acc[3][1] += a.w*w4.y; acc[3][2] += a.w*w4.z; acc[3][3] += a.w*w4.w;
    }
    float* dst = g_Wy + (size_t)b*64*6400;
    #pragma unroll
    for (int j = 0; j < 4; j++) {
        float4 v = make_float4(acc[0][j], acc[1][j], acc[2][j], acc[3][j]);
        *(float4*)&dst[(4*tx + j)*6400 + n0 + 4*ty] = v;
    }
    #pragma unroll
    for (int j = 0; j < 4; j++) {
        float s = 0.f, q = 0.f;
        #pragma unroll
        for (int r = 0; r < 4; r++) { s += acc[r][j]; q += acc[r][j]*acc[r][j]; }
        atomicAdd(&ssum[4*tx + j], s);
        atomicAdd(&ssq [4*tx + j], q);
    }
    __syncthreads();
    if (t < 64) {
        atomicAdd(&g_stats[t],      ssum[t]);
        atomicAdd(&g_stats[64 + t], ssq[t]);
    }
}

// ---------------- kernel 4: BN scale/shift ----------------------------------
__global__ void bnstats_kernel(const float* __restrict__ gamma,
                               const float* __restrict__ beta)
{
    int c = threadIdx.x;
    const float invN = 1.f / (float)(B_ * N_);
    float mean = g_stats[c] * invN;
    float var  = g_stats[64 + c] * invN - mean*mean;
    float sc   = gamma[c] * rsqrtf(var + 1e-5f);
    g_sc[c]      = sc;
    g_sc[64 + c] = beta[c] - mean*sc;
}

// ---------------- kernel 5: BN apply + residual ------------------------------
__global__ __launch_bounds__(256) void out_kernel(const float* __restrict__ x,
                                                  float* __restrict__ out)
{
    int i   = blockIdx.x * 256 + threadIdx.x;  // float4 index
    int idx = i * 4;
    int c   = (idx / 6400) & 63;
    float4 wy = *(const float4*)&g_Wy[idx];
    float4 xv = *(const float4*)&x[idx];
    float sc = g_sc[c], sh = g_sc[64 + c];
    float4 o;
    o.x = wy.x*sc + sh + xv.x;
    o.y = wy.y*sc + sh + xv.y;
    o.z = wy.z*sc + sh + xv.z;
    o.w = wy.w*sc + sh + xv.w;
    *(float4*)&out[idx] = o;
}

// ---------------- launch ------------------------------------------------------
extern "C" void kernel_launch(void* const* d_in, const int* in_sizes, int n_in,
                              void* d_out, int out_size)
{
    const float* x     = (const float*)d_in[0];
    const float* wt    = (const float*)d_in[1];
    const float* bt    = (const float*)d_in[2];
    const float* wp    = (const float*)d_in[3];
    const float* bp    = (const float*)d_in[4];
    const float* wg    = (const float*)d_in[5];
    const float* bg    = (const float*)d_in[6];
    const float* wW    = (const float*)d_in[7];
    const float* bW    = (const float*)d_in[8];
    const float* gamma = (const float*)d_in[9];
    const float* beta  = (const float*)d_in[10];

    dim3 grid(NTILES, B_);
    proj3_kernel <<<grid, 256>>>(x, wt, bt, wp, bp, wg, bg);
    flash_kernel <<<grid, 256>>>();
    convW_kernel <<<grid, 256>>>(wW, bW);
    bnstats_kernel<<<1, 64>>>(gamma, beta);
    out_kernel   <<<(B_*C_*N_)/4/256, 256>>>(x, (float*)d_out);
}

// round 5
// speedup vs baseline: 3.6582x; 3.6582x over previous
#include <cuda_runtime.h>
#include <cuda_bf16.h>
#include <cstdint>

#define B_ 4
#define C_ 64
#define N_ 6400

// ---------------- device-global scratch -------------------------------------
__device__ __align__(16) __nv_bfloat16 g_q_h[B_*N_*C_];   // [B][N][C]
__device__ __align__(16) __nv_bfloat16 g_q_l[B_*N_*C_];
__device__ __align__(16) __nv_bfloat16 g_k_h[B_*N_*C_];   // [B][N][C]
__device__ __align__(16) __nv_bfloat16 g_k_l[B_*N_*C_];
__device__ __align__(16) __nv_bfloat16 g_v_h[B_*C_*N_];   // [B][C][N]
__device__ __align__(16) __nv_bfloat16 g_v_l[B_*C_*N_];
__device__ float g_y    [B_*C_*N_];
__device__ float g_Wy   [B_*C_*N_];
__device__ float g_stats[2*C_];
__device__ float g_sc   [2*C_];

// ---------------- helpers ----------------------------------------------------
__device__ __forceinline__ uint32_t smem_u32(const void* p) {
    uint32_t a;
    asm("{ .reg .u64 t; cvta.to.shared.u64 t, %1; cvt.u32.u64 %0, t; }" : "=r"(a) : "l"(p));
    return a;
}
__device__ __forceinline__ void cpa16(uint32_t dst, const void* src) {
    asm volatile("cp.async.cg.shared.global [%0], [%1], 16;" :: "r"(dst), "l"(src));
}
__device__ __forceinline__ void mma_bf16(float* d, const uint32_t* a, const uint32_t* b) {
    asm volatile("mma.sync.aligned.m16n8k16.row.col.f32.bf16.bf16.f32 "
        "{%0,%1,%2,%3}, {%4,%5,%6,%7}, {%8,%9}, {%0,%1,%2,%3};"
        : "+f"(d[0]), "+f"(d[1]), "+f"(d[2]), "+f"(d[3])
        : "r"(a[0]), "r"(a[1]), "r"(a[2]), "r"(a[3]), "r"(b[0]), "r"(b[1]));
}
__device__ __forceinline__ void ldmx4(uint32_t* r, uint32_t a) {
    asm volatile("ldmatrix.sync.aligned.m8n8.x4.shared.b16 {%0,%1,%2,%3}, [%4];"
        : "=r"(r[0]), "=r"(r[1]), "=r"(r[2]), "=r"(r[3]) : "r"(a));
}
__device__ __forceinline__ void ldmx2(uint32_t* r, uint32_t a) {
    asm volatile("ldmatrix.sync.aligned.m8n8.x2.shared.b16 {%0,%1}, [%2];"
        : "=r"(r[0]), "=r"(r[1]) : "r"(a));
}
// pack (a,b) -> bf16x2 hi-plane + residual lo-plane (lo 16 bits = a)
__device__ __forceinline__ void split2(float a, float b, uint32_t& hi, uint32_t& lo) {
    uint32_t h;
    asm("cvt.rn.bf16x2.f32 %0, %1, %2;" : "=r"(h) : "f"(b), "f"(a));
    float ah = __uint_as_float(h << 16);
    float bh = __uint_as_float(h & 0xffff0000u);
    float al = a - ah, bl = b - bh;
    uint32_t l;
    asm("cvt.rn.bf16x2.f32 %0, %1, %2;" : "=r"(l) : "f"(bl), "f"(al));
    hi = h; lo = l;
}

// ---------------- kernel 1: projections -> bf16 hi/lo planes ----------------
__global__ __launch_bounds__(256) void proj3_kernel(
    const float* __restrict__ x,
    const float* __restrict__ wt, const float* __restrict__ bt,
    const float* __restrict__ wp, const float* __restrict__ bp,
    const float* __restrict__ wg, const float* __restrict__ bg)
{
    __shared__ __align__(16) float xs[64*68];
    __shared__ __align__(16) float ws[64*68];
    const int b  = blockIdx.y;
    const int n0 = blockIdx.x * 64;
    const int t  = threadIdx.x;
    const int tx = t & 15, ty = t >> 4;

    if (blockIdx.x == 0 && b == 0 && t < 128) g_stats[t] = 0.f;

    for (int i = t; i < 4096; i += 256) {
        int c = i >> 6, n = i & 63;
        xs[c*68 + n] = x[((size_t)b*64 + c)*6400 + n0 + n];
    }
    const float* W[3]  = {wt, wp, wg};
    const float* BV[3] = {bt, bp, bg};

    for (int m = 0; m < 3; m++) {
        __syncthreads();
        for (int i = t; i < 4096; i += 256) ws[(i & 63)*68 + (i >> 6)] = W[m][i];
        __syncthreads();

        float acc[4][4];
        #pragma unroll
        for (int j = 0; j < 4; j++) {
            float bb = BV[m][4*tx + j];
            #pragma unroll
            for (int r = 0; r < 4; r++) acc[r][j] = bb;
        }
        #pragma unroll 4
        for (int c = 0; c < 64; c++) {
            float4 a  = *(const float4*)&xs[c*68 + 4*ty];
            float4 w4 = *(const float4*)&ws[c*68 + 4*tx];
            acc[0][0] += a.x*w4.x; acc[0][1] += a.x*w4.y; acc[0][2] += a.x*w4.z; acc[0][3] += a.x*w4.w;
            acc[1][0] += a.y*w4.x; acc[1][1] += a.y*w4.y; acc[1][2] += a.y*w4.z; acc[1][3] += a.y*w4.w;
            acc[2][0] += a.z*w4.x; acc[2][1] += a.z*w4.y; acc[2][2] += a.z*w4.z; acc[2][3] += a.z*w4.w;
            acc[3][0] += a.w*w4.x; acc[3][1] += a.w*w4.y; acc[3][2] += a.w*w4.z; acc[3][3] += a.w*w4.w;
        }
        if (m < 2) {
            __nv_bfloat16* ph = (m == 0) ? g_q_h : g_k_h;
            __nv_bfloat16* pl = (m == 0) ? g_q_l : g_k_l;
            #pragma unroll
            for (int r = 0; r < 4; r++) {
                uint32_t h01, l01, h23, l23;
                split2(acc[r][0], acc[r][1], h01, l01);
                split2(acc[r][2], acc[r][3], h23, l23);
                size_t idx = ((size_t)b*6400 + n0 + 4*ty + r)*64 + 4*tx;
                *(uint2*)&ph[idx] = make_uint2(h01, h23);
                *(uint2*)&pl[idx] = make_uint2(l01, l23);
            }
        } else {
            #pragma unroll
            for (int j = 0; j < 4; j++) {
                uint32_t hA, lA, hB, lB;
                split2(acc[0][j], acc[1][j], hA, lA);
                split2(acc[2][j], acc[3][j], hB, lB);
                size_t idx = ((size_t)b*64 + 4*tx + j)*6400 + n0 + 4*ty;
                *(uint2*)&g_v_h[idx] = make_uint2(hA, hB);
                *(uint2*)&g_v_l[idx] = make_uint2(lA, lB);
            }
        }
    }
}

// ---------------- kernel 2: flash attention via mma.sync bf16 ---------------
// smem planes: 64 rows x 64 bf16 (128B rows, XOR-swizzled 16B chunks), 8KB each
#define PQH 0u
#define PQL 8192u
#define PKH 16384u
#define PKL 24576u
#define PVH 32768u
#define PVL 40960u

__device__ __forceinline__ void ld_plane(uint32_t dst, const __nv_bfloat16* src,
                                         int rowstride, int t)
{
    #pragma unroll
    for (int k = 0; k < 4; k++) {
        int idx = t + k*128;               // 512 chunks total
        int row = idx >> 3, ch = idx & 7;
        cpa16(dst + (uint32_t)row*128u + (uint32_t)((ch ^ (row & 7))*16),
              src + (size_t)row*rowstride + ch*8);
    }
}

__global__ __launch_bounds__(128, 3) void flash_kernel()
{
    __shared__ __align__(128) char smem[49152];
    const uint32_t sb = smem_u32(smem);
    const int t    = threadIdx.x;
    const int lane = t & 31;
    const int wid  = t >> 5;
    const int b    = blockIdx.y;
    const int n0   = blockIdx.x * 64;
    const int m0   = wid * 16;

    // initial loads: Q + chunk 0 of K/V
    ld_plane(sb + PQH, g_q_h + ((size_t)b*6400 + n0)*64, 64, t);
    ld_plane(sb + PQL, g_q_l + ((size_t)b*6400 + n0)*64, 64, t);
    ld_plane(sb + PKH, g_k_h + (size_t)b*6400*64, 64, t);
    ld_plane(sb + PKL, g_k_l + (size_t)b*6400*64, 64, t);
    ld_plane(sb + PVH, g_v_h + (size_t)b*64*6400, 6400, t);
    ld_plane(sb + PVL, g_v_l + (size_t)b*64*6400, 6400, t);
    asm volatile("cp.async.commit_group;" ::: "memory");

    // lane-derived ldmatrix address components
    const uint32_t ar  = (uint32_t)(lane & 7) + ((uint32_t)((lane >> 3) & 1) << 3);
    const uint32_t ax  = (uint32_t)((lane >> 4) & 1);
    const uint32_t br  = (uint32_t)(lane & 7);
    const uint32_t bx  = (uint32_t)((lane >> 3) & 1);
    const uint32_t axr = (uint32_t)(lane & 7);   // swizzle row bits for A

    uint32_t qh[4][4], ql[4][4];
    float O[8][4];
    #pragma unroll
    for (int i = 0; i < 8; i++)
        #pragma unroll
        for (int j = 0; j < 4; j++) O[i][j] = 0.f;
    float lsA = 0.f, lsB = 0.f;

    for (int i = 0; i < 100; i++) {
        asm volatile("cp.async.wait_group 0;" ::: "memory");
        __syncthreads();

        if (i == 0) {
            #pragma unroll
            for (int kb = 0; kb < 4; kb++) {
                uint32_t R  = (uint32_t)m0 + ar;
                uint32_t ch = ((uint32_t)(kb*2) + ax) ^ axr;
                ldmx4(qh[kb], sb + PQH + R*128u + ch*16u);
                ldmx4(ql[kb], sb + PQL + R*128u + ch*16u);
            }
        }

        // ---- S = Q K^T (3-term split) ----
        float S[8][4];
        #pragma unroll
        for (int nt = 0; nt < 8; nt++)
            #pragma unroll
            for (int j = 0; j < 4; j++) S[nt][j] = 0.f;

        #pragma unroll
        for (int nt = 0; nt < 8; nt++) {
            #pragma unroll
            for (int kb = 0; kb < 4; kb++) {
                uint32_t R    = (uint32_t)(nt*8) + br;
                uint32_t ch   = ((uint32_t)(kb*2) + bx) ^ br;
                uint32_t addr = sb + PKH + R*128u + ch*16u;
                uint32_t bh[2], bl[2];
                ldmx2(bh, addr);
                ldmx2(bl, addr + 8192u);
                mma_bf16(S[nt], qh[kb], bh);
                mma_bf16(S[nt], qh[kb], bl);
                mma_bf16(S[nt], ql[kb], bh);
            }
        }

        // ---- softmax numerator: exp (no max), pack into A-frags ----
        uint32_t ph[4][4], pl[4][4];
        #pragma unroll
        for (int nt = 0; nt < 8; nt++) {
            float p0 = __expf(S[nt][0]);
            float p1 = __expf(S[nt][1]);
            float p2 = __expf(S[nt][2]);
            float p3 = __expf(S[nt][3]);
            lsA += p0 + p1;
            lsB += p2 + p3;
            uint32_t h01, l01, h23, l23;
            split2(p0, p1, h01, l01);
            split2(p2, p3, h23, l23);
            int kb = nt >> 1, hf = (nt & 1) * 2;
            ph[kb][hf + 0] = h01; ph[kb][hf + 1] = h23;
            pl[kb][hf + 0] = l01; pl[kb][hf + 1] = l23;
        }

        // ---- O += P V (3-term split) ----
        #pragma unroll
        for (int ct = 0; ct < 8; ct++) {
            #pragma unroll
            for (int kb = 0; kb < 4; kb++) {
                uint32_t R    = (uint32_t)(ct*8) + br;
                uint32_t ch   = ((uint32_t)(kb*2) + bx) ^ br;
                uint32_t addr = sb + PVH + R*128u + ch*16u;
                uint32_t vh[2], vl[2];
                ldmx2(vh, addr);
                ldmx2(vl, addr + 8192u);
                mma_bf16(O[ct], ph[kb], vh);
                mma_bf16(O[ct], ph[kb], vl);
                mma_bf16(O[ct], pl[kb], vh);
            }
        }

        if (i < 99) {
            __syncthreads();
            ld_plane(sb + PKH, g_k_h + ((size_t)b*6400 + (i+1)*64)*64, 64, t);
            ld_plane(sb + PKL, g_k_l + ((size_t)b*6400 + (i+1)*64)*64, 64, t);
            ld_plane(sb + PVH, g_v_h + (size_t)b*64*6400 + (i+1)*64, 6400, t);
            ld_plane(sb + PVL, g_v_l + (size_t)b*64*6400 + (i+1)*64, 6400, t);
            asm volatile("cp.async.commit_group;" ::: "memory");
        }
    }

    // ---- normalize: row sums live in quads (lanes 4g..4g+3) ----
    lsA += __shfl_xor_sync(0xffffffffu, lsA, 1);
    lsA += __shfl_xor_sync(0xffffffffu, lsA, 2);
    lsB += __shfl_xor_sync(0xffffffffu, lsB, 1);
    lsB += __shfl_xor_sync(0xffffffffu, lsB, 2);
    const float invA = 1.f / lsA;
    const float invB = 1.f / lsB;

    __syncthreads();                        // done with K/V smem
    float* stg = (float*)(smem + PKH);      // 64x64 f32 staging = 16KB
    const int gq = lane >> 2, tq = lane & 3;
    #pragma unroll
    for (int ct = 0; ct < 8; ct++) {
        int c = ct*8 + 2*tq;
        stg[(c    )*64 + m0 + gq    ] = O[ct][0] * invA;
        stg[(c + 1)*64 + m0 + gq    ] = O[ct][1] * invA;
        stg[(c    )*64 + m0 + gq + 8] = O[ct][2] * invB;
        stg[(c + 1)*64 + m0 + gq + 8] = O[ct][3] * invB;
    }
    __syncthreads();
    for (int idx = t; idx < 1024; idx += 128) {
        int c = idx >> 4, chn = idx & 15;
        float4 v = *(float4*)&stg[c*64 + chn*4];
        *(float4*)&g_y[((size_t)b*64 + c)*6400 + n0 + chn*4] = v;
    }
}

// ---------------- kernel 3: W-conv + BN statistics ---------------------------
__global__ __launch_bounds__(256) void convW_kernel(
    const float* __restrict__ wW, const float* __restrict__ bW)
{
    __shared__ __align__(16) float ys[64*68];
    __shared__ __align__(16) float ws[64*68];
    __shared__ float ssum[64], ssq[64];
    const int b  = blockIdx.y;
    const int n0 = blockIdx.x * 64;
    const int t  = threadIdx.x;
    const int tx = t & 15, ty = t >> 4;

    const float* yb = g_y + (size_t)b*64*6400;
    for (int i = t; i < 4096; i += 256) {
        int c = i >> 6, n = i & 63;
        ys[c*68 + n] = yb[c*6400 + n0 + n];
    }
    for (int i = t; i < 4096; i += 256) ws[(i & 63)*68 + (i >> 6)] = wW[i];
    if (t < 64) { ssum[t] = 0.f; ssq[t] = 0.f; }
    __syncthreads();

    float acc[4][4];
    #pragma unroll
    for (int j = 0; j < 4; j++) {
        float bb = bW[4*tx + j];
        #pragma unroll
        for (int r = 0; r < 4; r++) acc[r][j] = bb;
    }
    #pragma unroll 4
    for (int c = 0; c < 64; c++) {
        float4 a  = *(const float4*)&ys[c*68 + 4*ty];
        float4 w4 = *(const float4*)&ws[c*68 + 4*tx];
        acc[0][0] += a.x*w4.x; acc[0][1] += a.x*w4.y; acc[0][2] += a.x*w4.z; acc[0][3] += a.x*w4.w;
        acc[1][0] += a.y*w4.x; acc[1][1] += a.y*w4.y; acc[1][2] += a.y*w4.z; acc[1][3] += a.y*w4.w;
        acc[2][0] += a.z*w4.x; acc[2][1] += a.z*w4.y; acc[2][2] += a.z*w4.z; acc[2][3] += a.z*w4.w;
        acc[3][0] += a.w*w4.x; acc[3][1] += a.w*w4.y; acc[3][2] += a.w*w4.z; acc[3][3] += a.w*w4.w;
    }
    float* dst = g_Wy + (size_t)b*64*6400;
    #pragma unroll
    for (int j = 0; j < 4; j++) {
        float4 v = make_float4(acc[0][j], acc[1][j], acc[2][j], acc[3][j]);
        *(float4*)&dst[(4*tx + j)*6400 + n0 + 4*ty] = v;
    }
    #pragma unroll
    for (int j = 0; j < 4; j++) {
        float s = 0.f, q = 0.f;
        #pragma unroll
        for (int r = 0; r < 4; r++) { s += acc[r][j]; q += acc[r][j]*acc[r][j]; }
        atomicAdd(&ssum[4*tx + j], s);
        atomicAdd(&ssq [4*tx + j], q);
    }
    __syncthreads();
    if (t < 64) {
        atomicAdd(&g_stats[t],      ssum[t]);
        atomicAdd(&g_stats[64 + t], ssq[t]);
    }
}

// ---------------- kernel 4: BN scale/shift -----------------------------------
__global__ void bnstats_kernel(const float* __restrict__ gamma,
                               const float* __restrict__ beta)
{
    int c = threadIdx.x;
    const float invN = 1.f / (float)(B_ * N_);
    float mean = g_stats[c] * invN;
    float var  = g_stats[64 + c] * invN - mean*mean;
    float sc   = gamma[c] * rsqrtf(var + 1e-5f);
    g_sc[c]      = sc;
    g_sc[64 + c] = beta[c] - mean*sc;
}

// ---------------- kernel 5: BN apply + residual -------------------------------
__global__ __launch_bounds__(256) void out_kernel(const float* __restrict__ x,
                                                  float* __restrict__ out)
{
    int i   = blockIdx.x * 256 + threadIdx.x;
    int idx = i * 4;
    int c   = (idx / 6400) & 63;
    float4 wy = *(const float4*)&g_Wy[idx];
    float4 xv = *(const float4*)&x[idx];
    float sc = g_sc[c], sh = g_sc[64 + c];
    float4 o;
    o.x = wy.x*sc + sh + xv.x;
    o.y = wy.y*sc + sh + xv.y;
    o.z = wy.z*sc + sh + xv.z;
    o.w = wy.w*sc + sh + xv.w;
    *(float4*)&out[idx] = o;
}

// ---------------- launch -------------------------------------------------------
extern "C" void kernel_launch(void* const* d_in, const int* in_sizes, int n_in,
                              void* d_out, int out_size)
{
    const float* x     = (const float*)d_in[0];
    const float* wt    = (const float*)d_in[1];
    const float* bt    = (const float*)d_in[2];
    const float* wp    = (const float*)d_in[3];
    const float* bp    = (const float*)d_in[4];
    const float* wg    = (const float*)d_in[5];
    const float* bg    = (const float*)d_in[6];
    const float* wW    = (const float*)d_in[7];
    const float* bW    = (const float*)d_in[8];
    const float* gamma = (const float*)d_in[9];
    const float* beta  = (const float*)d_in[10];

    dim3 gproj(100, B_);
    proj3_kernel <<<gproj, 256>>>(x, wt, bt, wp, bp, wg, bg);
    dim3 gflash(100, B_);
    flash_kernel <<<gflash, 128>>>();
    convW_kernel <<<gproj, 256>>>(wW, bW);
    bnstats_kernel<<<1, 64>>>(gamma, beta);
    out_kernel   <<<(B_*C_*N_)/4/256, 256>>>(x, (float*)d_out);
}

// round 6
// speedup vs baseline: 3.7559x; 1.0267x over previous
#include <cuda_runtime.h>
#include <cuda_bf16.h>
#include <cstdint>

#define B_ 4
#define C_ 64
#define N_ 6400

// ---------------- device-global scratch -------------------------------------
__device__ __align__(16) __nv_bfloat16 g_q_h[B_*N_*C_];   // [B][N][C]
__device__ __align__(16) __nv_bfloat16 g_q_l[B_*N_*C_];
__device__ __align__(16) __nv_bfloat16 g_k_h[B_*N_*C_];   // [B][N][C]
__device__ __align__(16) __nv_bfloat16 g_k_l[B_*N_*C_];
__device__ __align__(16) __nv_bfloat16 g_v_h[B_*C_*N_];   // [B][C][N]
__device__ __align__(16) __nv_bfloat16 g_v_l[B_*C_*N_];
__device__ float g_y    [B_*C_*N_];
__device__ float g_Wy   [B_*C_*N_];
__device__ float g_stats[2*C_];
__device__ float g_sc   [2*C_];

// ---------------- helpers ----------------------------------------------------
__device__ __forceinline__ uint32_t smem_u32(const void* p) {
    uint32_t a;
    asm("{ .reg .u64 t; cvta.to.shared.u64 t, %1; cvt.u32.u64 %0, t; }" : "=r"(a) : "l"(p));
    return a;
}
__device__ __forceinline__ void cpa16(uint32_t dst, const void* src) {
    asm volatile("cp.async.cg.shared.global [%0], [%1], 16;" :: "r"(dst), "l"(src));
}
__device__ __forceinline__ void mma_bf16(float* d, const uint32_t* a, const uint32_t* b) {
    asm volatile("mma.sync.aligned.m16n8k16.row.col.f32.bf16.bf16.f32 "
        "{%0,%1,%2,%3}, {%4,%5,%6,%7}, {%8,%9}, {%0,%1,%2,%3};"
        : "+f"(d[0]), "+f"(d[1]), "+f"(d[2]), "+f"(d[3])
        : "r"(a[0]), "r"(a[1]), "r"(a[2]), "r"(a[3]), "r"(b[0]), "r"(b[1]));
}
__device__ __forceinline__ void ldmx4(uint32_t* r, uint32_t a) {
    asm volatile("ldmatrix.sync.aligned.m8n8.x4.shared.b16 {%0,%1,%2,%3}, [%4];"
        : "=r"(r[0]), "=r"(r[1]), "=r"(r[2]), "=r"(r[3]) : "r"(a));
}
// pack (a,b) -> bf16x2 hi-plane + residual lo-plane (lo 16 bits = a)
__device__ __forceinline__ void split2(float a, float b, uint32_t& hi, uint32_t& lo) {
    uint32_t h;
    asm("cvt.rn.bf16x2.f32 %0, %1, %2;" : "=r"(h) : "f"(b), "f"(a));
    float ah = __uint_as_float(h << 16);
    float bh = __uint_as_float(h & 0xffff0000u);
    float al = a - ah, bl = b - bh;
    uint32_t l;
    asm("cvt.rn.bf16x2.f32 %0, %1, %2;" : "=r"(l) : "f"(bl), "f"(al));
    hi = h; lo = l;
}

// ---------------- kernel 1: projections -> bf16 hi/lo planes ----------------
__global__ __launch_bounds__(256) void proj3_kernel(
    const float* __restrict__ x,
    const float* __restrict__ wt, const float* __restrict__ bt,
    const float* __restrict__ wp, const float* __restrict__ bp,
    const float* __restrict__ wg, const float* __restrict__ bg)
{
    __shared__ __align__(16) float xs[64*68];
    __shared__ __align__(16) float ws[64*68];
    const int b  = blockIdx.y;
    const int n0 = blockIdx.x * 64;
    const int t  = threadIdx.x;
    const int tx = t & 15, ty = t >> 4;

    if (blockIdx.x == 0 && b == 0 && t < 128) g_stats[t] = 0.f;

    for (int i = t; i < 4096; i += 256) {
        int c = i >> 6, n = i & 63;
        xs[c*68 + n] = x[((size_t)b*64 + c)*6400 + n0 + n];
    }
    const float* W[3]  = {wt, wp, wg};
    const float* BV[3] = {bt, bp, bg};

    for (int m = 0; m < 3; m++) {
        __syncthreads();
        for (int i = t; i < 4096; i += 256) ws[(i & 63)*68 + (i >> 6)] = W[m][i];
        __syncthreads();

        float acc[4][4];
        #pragma unroll
        for (int j = 0; j < 4; j++) {
            float bb = BV[m][4*tx + j];
            #pragma unroll
            for (int r = 0; r < 4; r++) acc[r][j] = bb;
        }
        #pragma unroll 4
        for (int c = 0; c < 64; c++) {
            float4 a  = *(const float4*)&xs[c*68 + 4*ty];
            float4 w4 = *(const float4*)&ws[c*68 + 4*tx];
            acc[0][0] += a.x*w4.x; acc[0][1] += a.x*w4.y; acc[0][2] += a.x*w4.z; acc[0][3] += a.x*w4.w;
            acc[1][0] += a.y*w4.x; acc[1][1] += a.y*w4.y; acc[1][2] += a.y*w4.z; acc[1][3] += a.y*w4.w;
            acc[2][0] += a.z*w4.x; acc[2][1] += a.z*w4.y; acc[2][2] += a.z*w4.z; acc[2][3] += a.z*w4.w;
            acc[3][0] += a.w*w4.x; acc[3][1] += a.w*w4.y; acc[3][2] += a.w*w4.z; acc[3][3] += a.w*w4.w;
        }
        if (m < 2) {
            __nv_bfloat16* ph = (m == 0) ? g_q_h : g_k_h;
            __nv_bfloat16* pl = (m == 0) ? g_q_l : g_k_l;
            #pragma unroll
            for (int r = 0; r < 4; r++) {
                uint32_t h01, l01, h23, l23;
                split2(acc[r][0], acc[r][1], h01, l01);
                split2(acc[r][2], acc[r][3], h23, l23);
                size_t idx = ((size_t)b*6400 + n0 + 4*ty + r)*64 + 4*tx;
                *(uint2*)&ph[idx] = make_uint2(h01, h23);
                *(uint2*)&pl[idx] = make_uint2(l01, l23);
            }
        } else {
            #pragma unroll
            for (int j = 0; j < 4; j++) {
                uint32_t hA, lA, hB, lB;
                split2(acc[0][j], acc[1][j], hA, lA);
                split2(acc[2][j], acc[3][j], hB, lB);
                size_t idx = ((size_t)b*64 + 4*tx + j)*6400 + n0 + 4*ty;
                *(uint2*)&g_v_h[idx] = make_uint2(hA, hB);
                *(uint2*)&g_v_l[idx] = make_uint2(lA, lB);
            }
        }
    }
}

// ---------------- kernel 2: flash attention via mma.sync bf16 ---------------
// smem planes: 64 rows x 64 bf16 (128B rows, XOR-swizzled 16B chunks), 8KB each
#define PQH 0u
#define PQL 8192u
#define PKH 16384u
#define PKL 24576u
#define PVH 32768u
#define PVL 40960u

__device__ __forceinline__ void ld_plane(uint32_t dst, const __nv_bfloat16* src,
                                         int rowstride, int t)
{
    #pragma unroll
    for (int k = 0; k < 4; k++) {
        int idx = t + k*128;               // 512 chunks total
        int row = idx >> 3, ch = idx & 7;
        cpa16(dst + (uint32_t)row*128u + (uint32_t)((ch ^ (row & 7))*16),
              src + (size_t)row*rowstride + ch*8);
    }
}

__global__ __launch_bounds__(128, 3) void flash_kernel()
{
    __shared__ __align__(128) char smem[49152];
    const uint32_t sb = smem_u32(smem);
    const int t    = threadIdx.x;
    const int lane = t & 31;
    const int wid  = t >> 5;
    const int b    = blockIdx.y;
    const int n0   = blockIdx.x * 64;
    const int m0   = wid * 16;

    // prologue: group0 = {Q, K0}, group1 = {V0}
    ld_plane(sb + PQH, g_q_h + ((size_t)b*6400 + n0)*64, 64, t);
    ld_plane(sb + PQL, g_q_l + ((size_t)b*6400 + n0)*64, 64, t);
    ld_plane(sb + PKH, g_k_h + (size_t)b*6400*64, 64, t);
    ld_plane(sb + PKL, g_k_l + (size_t)b*6400*64, 64, t);
    asm volatile("cp.async.commit_group;" ::: "memory");
    ld_plane(sb + PVH, g_v_h + (size_t)b*64*6400, 6400, t);
    ld_plane(sb + PVL, g_v_l + (size_t)b*64*6400, 6400, t);
    asm volatile("cp.async.commit_group;" ::: "memory");

    // lane-derived ldmatrix address components
    const uint32_t ar   = (uint32_t)(lane & 7) + ((uint32_t)((lane >> 3) & 1) << 3);
    const uint32_t ax   = (uint32_t)((lane >> 4) & 1);
    const uint32_t axr  = (uint32_t)(lane & 7);
    const uint32_t br   = (uint32_t)(lane & 7);
    const uint32_t bx   = (uint32_t)((lane >> 3) & 1);
    const uint32_t bpl  = ((uint32_t)(lane >> 4) & 1) * 8192u;  // lanes 16-31 -> lo plane

    uint32_t qh[4][4], ql[4][4];
    float O[8][4];
    #pragma unroll
    for (int i = 0; i < 8; i++)
        #pragma unroll
        for (int j = 0; j < 4; j++) O[i][j] = 0.f;
    float lsA = 0.f, lsB = 0.f;

    #pragma unroll 1
    for (int i = 0; i < 100; i++) {
        // K(i) ready (leave V(i) pending)
        asm volatile("cp.async.wait_group 1;" ::: "memory");
        __syncthreads();

        if (i == 0) {
            #pragma unroll
            for (int kb = 0; kb < 4; kb++) {
                uint32_t R  = (uint32_t)m0 + ar;
                uint32_t ch = ((uint32_t)(kb*2) + ax) ^ axr;
                ldmx4(qh[kb], sb + PQH + R*128u + ch*16u);
                ldmx4(ql[kb], sb + PQL + R*128u + ch*16u);
            }
        }

        // ---- S = Q K^T : per kb load 8 B-frags (hi+lo fused), term-major MMA ----
        float S[8][4];
        #pragma unroll
        for (int nt = 0; nt < 8; nt++)
            #pragma unroll
            for (int j = 0; j < 4; j++) S[nt][j] = 0.f;

        #pragma unroll
        for (int kb = 0; kb < 4; kb++) {
            uint32_t kf[8][4];
            #pragma unroll
            for (int nt = 0; nt < 8; nt++) {
                uint32_t R  = (uint32_t)(nt*8) + br;
                uint32_t ch = ((uint32_t)(kb*2) + bx) ^ br;
                ldmx4(kf[nt], sb + PKH + bpl + R*128u + ch*16u);
            }
            #pragma unroll
            for (int nt = 0; nt < 8; nt++) mma_bf16(S[nt], qh[kb], &kf[nt][0]);
            #pragma unroll
            for (int nt = 0; nt < 8; nt++) mma_bf16(S[nt], qh[kb], &kf[nt][2]);
            #pragma unroll
            for (int nt = 0; nt < 8; nt++) mma_bf16(S[nt], ql[kb], &kf[nt][0]);
        }

        __syncthreads();                       // all warps done reading K
        if (i < 99) {                          // prefetch K(i+1) over softmax+PV
            ld_plane(sb + PKH, g_k_h + ((size_t)b*6400 + (i+1)*64)*64, 64, t);
            ld_plane(sb + PKL, g_k_l + ((size_t)b*6400 + (i+1)*64)*64, 64, t);
            asm volatile("cp.async.commit_group;" ::: "memory");
        }

        // ---- softmax numerator: exp (no max), pack into A-frags ----
        uint32_t ph[4][4], pl[4][4];
        #pragma unroll
        for (int nt = 0; nt < 8; nt++) {
            float p0 = __expf(S[nt][0]);
            float p1 = __expf(S[nt][1]);
            float p2 = __expf(S[nt][2]);
            float p3 = __expf(S[nt][3]);
            lsA += p0 + p1;
            lsB += p2 + p3;
            uint32_t h01, l01, h23, l23;
            split2(p0, p1, h01, l01);
            split2(p2, p3, h23, l23);
            int kb = nt >> 1, hf = (nt & 1) * 2;
            ph[kb][hf + 0] = h01; ph[kb][hf + 1] = h23;
            pl[kb][hf + 0] = l01; pl[kb][hf + 1] = l23;
        }

        // V(i) ready (leave K(i+1) pending)
        if (i < 99) { asm volatile("cp.async.wait_group 1;" ::: "memory"); }
        else        { asm volatile("cp.async.wait_group 0;" ::: "memory"); }
        __syncthreads();

        // ---- O += P V : same fused-B, term-major pattern ----
        #pragma unroll
        for (int kb = 0; kb < 4; kb++) {
            uint32_t vf[8][4];
            #pragma unroll
            for (int ct = 0; ct < 8; ct++) {
                uint32_t R  = (uint32_t)(ct*8) + br;
                uint32_t ch = ((uint32_t)(kb*2) + bx) ^ br;
                ldmx4(vf[ct], sb + PVH + bpl + R*128u + ch*16u);
            }
            #pragma unroll
            for (int ct = 0; ct < 8; ct++) mma_bf16(O[ct], ph[kb], &vf[ct][0]);
            #pragma unroll
            for (int ct = 0; ct < 8; ct++) mma_bf16(O[ct], ph[kb], &vf[ct][2]);
            #pragma unroll
            for (int ct = 0; ct < 8; ct++) mma_bf16(O[ct], pl[kb], &vf[ct][0]);
        }

        __syncthreads();                       // all warps done reading V
        if (i < 99) {                          // prefetch V(i+1) over next S-GEMM
            ld_plane(sb + PVH, g_v_h + (size_t)b*64*6400 + (i+1)*64, 6400, t);
            ld_plane(sb + PVL, g_v_l + (size_t)b*64*6400 + (i+1)*64, 6400, t);
            asm volatile("cp.async.commit_group;" ::: "memory");
        }
    }

    // ---- normalize: row sums live in quads ----
    lsA += __shfl_xor_sync(0xffffffffu, lsA, 1);
    lsA += __shfl_xor_sync(0xffffffffu, lsA, 2);
    lsB += __shfl_xor_sync(0xffffffffu, lsB, 1);
    lsB += __shfl_xor_sync(0xffffffffu, lsB, 2);
    const float invA = 1.f / lsA;
    const float invB = 1.f / lsB;

    __syncthreads();
    float* stg = (float*)(smem + PKH);      // 64x64 f32 staging = 16KB
    const int gq = lane >> 2, tq = lane & 3;
    #pragma unroll
    for (int ct = 0; ct < 8; ct++) {
        int c = ct*8 + 2*tq;
        stg[(c    )*64 + m0 + gq    ] = O[ct][0] * invA;
        stg[(c + 1)*64 + m0 + gq    ] = O[ct][1] * invA;
        stg[(c    )*64 + m0 + gq + 8] = O[ct][2] * invB;
        stg[(c + 1)*64 + m0 + gq + 8] = O[ct][3] * invB;
    }
    __syncthreads();
    for (int idx = t; idx < 1024; idx += 128) {
        int c = idx >> 4, chn = idx & 15;
        float4 v = *(float4*)&stg[c*64 + chn*4];
        *(float4*)&g_y[((size_t)b*64 + c)*6400 + n0 + chn*4] = v;
    }
}

// ---------------- kernel 3: W-conv + BN statistics ---------------------------
__global__ __launch_bounds__(256) void convW_kernel(
    const float* __restrict__ wW, const float* __restrict__ bW)
{
    __shared__ __align__(16) float ys[64*68];
    __shared__ __align__(16) float ws[64*68];
    __shared__ float ssum[64], ssq[64];
    const int b  = blockIdx.y;
    const int n0 = blockIdx.x * 64;
    const int t  = threadIdx.x;
    const int tx = t & 15, ty = t >> 4;

    const float* yb = g_y + (size_t)b*64*6400;
    for (int i = t; i < 4096; i += 256) {
        int c = i >> 6, n = i & 63;
        ys[c*68 + n] = yb[c*6400 + n0 + n];
    }
    for (int i = t; i < 4096; i += 256) ws[(i & 63)*68 + (i >> 6)] = wW[i];
    if (t < 64) { ssum[t] = 0.f; ssq[t] = 0.f; }
    __syncthreads();

    float acc[4][4];
    #pragma unroll
    for (int j = 0; j < 4; j++) {
        float bb = bW[4*tx + j];
        #pragma unroll
        for (int r = 0; r < 4; r++) acc[r][j] = bb;
    }
    #pragma unroll 4
    for (int c = 0; c < 64; c++) {
        float4 a  = *(const float4*)&ys[c*68 + 4*ty];
        float4 w4 = *(const float4*)&ws[c*68 + 4*tx];
        acc[0][0] += a.x*w4.x; acc[0][1] += a.x*w4.y; acc[0][2] += a.x*w4.z; acc[0][3] += a.x*w4.w;
        acc[1][0] += a.y*w4.x; acc[1][1] += a.y*w4.y; acc[1][2] += a.y*w4.z; acc[1][3] += a.y*w4.w;
        acc[2][0] += a.z*w4.x; acc[2][1] += a.z*w4.y; acc[2][2] += a.z*w4.z; acc[2][3] += a.z*w4.w;
        acc[3][0] += a.w*w4.x; acc[3][1] += a.w*w4.y; acc[3][2] += a.w*w4.z; acc[3][3] += a.w*w4.w;
    }
    float* dst = g_Wy + (size_t)b*64*6400;
    #pragma unroll
    for (int j = 0; j < 4; j++) {
        float4 v = make_float4(acc[0][j], acc[1][j], acc[2][j], acc[3][j]);
        *(float4*)&dst[(4*tx + j)*6400 + n0 + 4*ty] = v;
    }
    #pragma unroll
    for (int j = 0; j < 4; j++) {
        float s = 0.f, q = 0.f;
        #pragma unroll
        for (int r = 0; r < 4; r++) { s += acc[r][j]; q += acc[r][j]*acc[r][j]; }
        atomicAdd(&ssum[4*tx + j], s);
        atomicAdd(&ssq [4*tx + j], q);
    }
    __syncthreads();
    if (t < 64) {
        atomicAdd(&g_stats[t],      ssum[t]);
        atomicAdd(&g_stats[64 + t], ssq[t]);
    }
}

// ---------------- kernel 4: BN scale/shift -----------------------------------
__global__ void bnstats_kernel(const float* __restrict__ gamma,
                               const float* __restrict__ beta)
{
    int c = threadIdx.x;
    const float invN = 1.f / (float)(B_ * N_);
    float mean = g_stats[c] * invN;
    float var  = g_stats[64 + c] * invN - mean*mean;
    float sc   = gamma[c] * rsqrtf(var + 1e-5f);
    g_sc[c]      = sc;
    g_sc[64 + c] = beta[c] - mean*sc;
}

// ---------------- kernel 5: BN apply + residual -------------------------------
__global__ __launch_bounds__(256) void out_kernel(const float* __restrict__ x,
                                                  float* __restrict__ out)
{
    int i   = blockIdx.x * 256 + threadIdx.x;
    int idx = i * 4;
    int c   = (idx / 6400) & 63;
    float4 wy = *(const float4*)&g_Wy[idx];
    float4 xv = *(const float4*)&x[idx];
    float sc = g_sc[c], sh = g_sc[64 + c];
    float4 o;
    o.x = wy.x*sc + sh + xv.x;
    o.y = wy.y*sc + sh + xv.y;
    o.z = wy.z*sc + sh + xv.z;
    o.w = wy.w*sc + sh + xv.w;
    *(float4*)&out[idx] = o;
}

// ---------------- launch -------------------------------------------------------
extern "C" void kernel_launch(void* const* d_in, const int* in_sizes, int n_in,
                              void* d_out, int out_size)
{
    const float* x     = (const float*)d_in[0];
    const float* wt    = (const float*)d_in[1];
    const float* bt    = (const float*)d_in[2];
    const float* wp    = (const float*)d_in[3];
    const float* bp    = (const float*)d_in[4];
    const float* wg    = (const float*)d_in[5];
    const float* bg    = (const float*)d_in[6];
    const float* wW    = (const float*)d_in[7];
    const float* bW    = (const float*)d_in[8];
    const float* gamma = (const float*)d_in[9];
    const float* beta  = (const float*)d_in[10];

    dim3 gproj(100, B_);
    proj3_kernel <<<gproj, 256>>>(x, wt, bt, wp, bp, wg, bg);
    dim3 gflash(100, B_);
    flash_kernel <<<gflash, 128>>>();
    convW_kernel <<<gproj, 256>>>(wW, bW);
    bnstats_kernel<<<1, 64>>>(gamma, beta);
    out_kernel   <<<(B_*C_*N_)/4/256, 256>>>(x, (float*)d_out);
}

// round 7
// speedup vs baseline: 4.1872x; 1.1148x over previous
#include <cuda_runtime.h>
#include <cuda_bf16.h>
#include <cstdint>

#define B_ 4
#define C_ 64
#define N_ 6400

// ---------------- device-global scratch -------------------------------------
__device__ __align__(16) __nv_bfloat16 g_q_h[B_*N_*C_];   // [B][N][C]
__device__ __align__(16) __nv_bfloat16 g_q_l[B_*N_*C_];
__device__ __align__(16) __nv_bfloat16 g_k_h[B_*N_*C_];   // [B][N][C]
__device__ __align__(16) __nv_bfloat16 g_k_l[B_*N_*C_];
__device__ __align__(16) __nv_bfloat16 g_v_h[B_*C_*N_];   // [B][C][N]
__device__ __align__(16) __nv_bfloat16 g_v_l[B_*C_*N_];
__device__ float g_y    [B_*C_*N_];
__device__ float g_Wy   [B_*C_*N_];
__device__ float g_stats[2*C_];
__device__ float g_sc   [2*C_];

// ---------------- helpers ----------------------------------------------------
__device__ __forceinline__ uint32_t smem_u32(const void* p) {
    uint32_t a;
    asm("{ .reg .u64 t; cvta.to.shared.u64 t, %1; cvt.u32.u64 %0, t; }" : "=r"(a) : "l"(p));
    return a;
}
__device__ __forceinline__ void cpa16(uint32_t dst, const void* src) {
    asm volatile("cp.async.cg.shared.global [%0], [%1], 16;" :: "r"(dst), "l"(src));
}
__device__ __forceinline__ void mma_bf16(float* d, const uint32_t* a, const uint32_t* b) {
    asm volatile("mma.sync.aligned.m16n8k16.row.col.f32.bf16.bf16.f32 "
        "{%0,%1,%2,%3}, {%4,%5,%6,%7}, {%8,%9}, {%0,%1,%2,%3};"
        : "+f"(d[0]), "+f"(d[1]), "+f"(d[2]), "+f"(d[3])
        : "r"(a[0]), "r"(a[1]), "r"(a[2]), "r"(a[3]), "r"(b[0]), "r"(b[1]));
}
__device__ __forceinline__ void ldmx4(uint32_t* r, uint32_t a) {
    asm volatile("ldmatrix.sync.aligned.m8n8.x4.shared.b16 {%0,%1,%2,%3}, [%4];"
        : "=r"(r[0]), "=r"(r[1]), "=r"(r[2]), "=r"(r[3]) : "r"(a));
}
// pack (a,b) -> bf16x2 hi-plane + residual lo-plane (lo 16 bits = a)
__device__ __forceinline__ void split2(float a, float b, uint32_t& hi, uint32_t& lo) {
    uint32_t h;
    asm("cvt.rn.bf16x2.f32 %0, %1, %2;" : "=r"(h) : "f"(b), "f"(a));
    float ah = __uint_as_float(h << 16);
    float bh = __uint_as_float(h & 0xffff0000u);
    float al = a - ah, bl = b - bh;
    uint32_t l;
    asm("cvt.rn.bf16x2.f32 %0, %1, %2;" : "=r"(l) : "f"(bl), "f"(al));
    hi = h; lo = l;
}
__device__ __forceinline__ uint32_t pack_bf16x2(float a, float b) {
    uint32_t h;
    asm("cvt.rn.bf16x2.f32 %0, %1, %2;" : "=r"(h) : "f"(b), "f"(a));
    return h;
}

// ---------------- kernel 1: projections -> bf16 hi/lo planes ----------------
__global__ __launch_bounds__(256) void proj3_kernel(
    const float* __restrict__ x,
    const float* __restrict__ wt, const float* __restrict__ bt,
    const float* __restrict__ wp, const float* __restrict__ bp,
    const float* __restrict__ wg, const float* __restrict__ bg)
{
    __shared__ __align__(16) float xs[64*68];
    __shared__ __align__(16) float ws[64*68];
    const int b  = blockIdx.y;
    const int n0 = blockIdx.x * 64;
    const int t  = threadIdx.x;
    const int tx = t & 15, ty = t >> 4;

    if (blockIdx.x == 0 && b == 0 && t < 128) g_stats[t] = 0.f;

    for (int i = t; i < 4096; i += 256) {
        int c = i >> 6, n = i & 63;
        xs[c*68 + n] = x[((size_t)b*64 + c)*6400 + n0 + n];
    }
    const float* W[3]  = {wt, wp, wg};
    const float* BV[3] = {bt, bp, bg};

    for (int m = 0; m < 3; m++) {
        __syncthreads();
        for (int i = t; i < 4096; i += 256) ws[(i & 63)*68 + (i >> 6)] = W[m][i];
        __syncthreads();

        float acc[4][4];
        #pragma unroll
        for (int j = 0; j < 4; j++) {
            float bb = BV[m][4*tx + j];
            #pragma unroll
            for (int r = 0; r < 4; r++) acc[r][j] = bb;
        }
        #pragma unroll 4
        for (int c = 0; c < 64; c++) {
            float4 a  = *(const float4*)&xs[c*68 + 4*ty];
            float4 w4 = *(const float4*)&ws[c*68 + 4*tx];
            acc[0][0] += a.x*w4.x; acc[0][1] += a.x*w4.y; acc[0][2] += a.x*w4.z; acc[0][3] += a.x*w4.w;
            acc[1][0] += a.y*w4.x; acc[1][1] += a.y*w4.y; acc[1][2] += a.y*w4.z; acc[1][3] += a.y*w4.w;
            acc[2][0] += a.z*w4.x; acc[2][1] += a.z*w4.y; acc[2][2] += a.z*w4.z; acc[2][3] += a.z*w4.w;
            acc[3][0] += a.w*w4.x; acc[3][1] += a.w*w4.y; acc[3][2] += a.w*w4.z; acc[3][3] += a.w*w4.w;
        }
        if (m < 2) {
            __nv_bfloat16* ph = (m == 0) ? g_q_h : g_k_h;
            __nv_bfloat16* pl = (m == 0) ? g_q_l : g_k_l;
            #pragma unroll
            for (int r = 0; r < 4; r++) {
                uint32_t h01, l01, h23, l23;
                split2(acc[r][0], acc[r][1], h01, l01);
                split2(acc[r][2], acc[r][3], h23, l23);
                size_t idx = ((size_t)b*6400 + n0 + 4*ty + r)*64 + 4*tx;
                *(uint2*)&ph[idx] = make_uint2(h01, h23);
                *(uint2*)&pl[idx] = make_uint2(l01, l23);
            }
        } else {
            #pragma unroll
            for (int j = 0; j < 4; j++) {
                uint32_t hA, lA, hB, lB;
                split2(acc[0][j], acc[1][j], hA, lA);
                split2(acc[2][j], acc[3][j], hB, lB);
                size_t idx = ((size_t)b*64 + 4*tx + j)*6400 + n0 + 4*ty;
                *(uint2*)&g_v_h[idx] = make_uint2(hA, hB);
                *(uint2*)&g_v_l[idx] = make_uint2(lA, lB);
            }
        }
    }
}

// ---------------- kernel 2: flash attention via mma.sync bf16 ---------------
// smem planes: 64 rows x 64 bf16 (128B rows, XOR-swizzled 16B chunks), 8KB each
#define PQH 0u
#define PQL 8192u
#define PKH 16384u
#define PKL 24576u
#define PVH 32768u
#define PVL 40960u

__device__ __forceinline__ void ld_plane(uint32_t dst, const __nv_bfloat16* src,
                                         int rowstride, int t)
{
    #pragma unroll
    for (int k = 0; k < 4; k++) {
        int idx = t + k*128;               // 512 chunks total
        int row = idx >> 3, ch = idx & 7;
        cpa16(dst + (uint32_t)row*128u + (uint32_t)((ch ^ (row & 7))*16),
              src + (size_t)row*rowstride + ch*8);
    }
}

__global__ __launch_bounds__(128, 4) void flash_kernel()
{
    __shared__ __align__(128) char smem[49152];
    const uint32_t sb = smem_u32(smem);
    const int t    = threadIdx.x;
    const int lane = t & 31;
    const int wid  = t >> 5;
    const int b    = blockIdx.y;
    const int n0   = blockIdx.x * 64;
    const int m0   = wid * 16;

    // prologue: group0 = {Q, K0}, group1 = {V0}
    ld_plane(sb + PQH, g_q_h + ((size_t)b*6400 + n0)*64, 64, t);
    ld_plane(sb + PQL, g_q_l + ((size_t)b*6400 + n0)*64, 64, t);
    ld_plane(sb + PKH, g_k_h + (size_t)b*6400*64, 64, t);
    ld_plane(sb + PKL, g_k_l + (size_t)b*6400*64, 64, t);
    asm volatile("cp.async.commit_group;" ::: "memory");
    ld_plane(sb + PVH, g_v_h + (size_t)b*64*6400, 6400, t);
    ld_plane(sb + PVL, g_v_l + (size_t)b*64*6400, 6400, t);
    asm volatile("cp.async.commit_group;" ::: "memory");

    // lane-derived ldmatrix address components
    const uint32_t ar   = (uint32_t)(lane & 7) + ((uint32_t)((lane >> 3) & 1) << 3);
    const uint32_t ax   = (uint32_t)((lane >> 4) & 1);
    const uint32_t axr  = (uint32_t)(lane & 7);
    const uint32_t br   = (uint32_t)(lane & 7);
    const uint32_t bx   = (uint32_t)((lane >> 3) & 1);
    const uint32_t bpl  = ((uint32_t)(lane >> 4) & 1) * 8192u;  // lanes 16-31 -> lo plane

    uint32_t qh[4][4], ql[4][4];
    float O[8][4];
    #pragma unroll
    for (int i = 0; i < 8; i++)
        #pragma unroll
        for (int j = 0; j < 4; j++) O[i][j] = 0.f;
    float lsA = 0.f, lsB = 0.f;

    #pragma unroll 1
    for (int i = 0; i < 100; i++) {
        // K(i) ready (leave V(i) pending)
        asm volatile("cp.async.wait_group 1;" ::: "memory");
        __syncthreads();

        if (i == 0) {
            #pragma unroll
            for (int kb = 0; kb < 4; kb++) {
                uint32_t R  = (uint32_t)m0 + ar;
                uint32_t ch = ((uint32_t)(kb*2) + ax) ^ axr;
                ldmx4(qh[kb], sb + PQH + R*128u + ch*16u);
                ldmx4(ql[kb], sb + PQL + R*128u + ch*16u);
            }
        }

        // ---- S = Q K^T : 3-term split, fused hi/lo B-frag loads ----
        float S[8][4];
        #pragma unroll
        for (int nt = 0; nt < 8; nt++)
            #pragma unroll
            for (int j = 0; j < 4; j++) S[nt][j] = 0.f;

        #pragma unroll
        for (int kb = 0; kb < 4; kb++) {
            uint32_t kf[8][4];
            #pragma unroll
            for (int nt = 0; nt < 8; nt++) {
                uint32_t R  = (uint32_t)(nt*8) + br;
                uint32_t ch = ((uint32_t)(kb*2) + bx) ^ br;
                ldmx4(kf[nt], sb + PKH + bpl + R*128u + ch*16u);
            }
            #pragma unroll
            for (int nt = 0; nt < 8; nt++) mma_bf16(S[nt], qh[kb], &kf[nt][0]);
            #pragma unroll
            for (int nt = 0; nt < 8; nt++) mma_bf16(S[nt], qh[kb], &kf[nt][2]);
            #pragma unroll
            for (int nt = 0; nt < 8; nt++) mma_bf16(S[nt], ql[kb], &kf[nt][0]);
        }

        __syncthreads();                       // all warps done reading K
        if (i < 99) {                          // prefetch K(i+1) over softmax+PV
            ld_plane(sb + PKH, g_k_h + ((size_t)b*6400 + (i+1)*64)*64, 64, t);
            ld_plane(sb + PKL, g_k_l + ((size_t)b*6400 + (i+1)*64)*64, 64, t);
            asm volatile("cp.async.commit_group;" ::: "memory");
        }

        // ---- softmax numerator: exp (no max), hi-only P pack ----
        uint32_t ph[4][4];
        #pragma unroll
        for (int nt = 0; nt < 8; nt++) {
            float p0 = __expf(S[nt][0]);
            float p1 = __expf(S[nt][1]);
            float p2 = __expf(S[nt][2]);
            float p3 = __expf(S[nt][3]);
            lsA += p0 + p1;
            lsB += p2 + p3;
            int kb = nt >> 1, hf = (nt & 1) * 2;
            ph[kb][hf + 0] = pack_bf16x2(p0, p1);
            ph[kb][hf + 1] = pack_bf16x2(p2, p3);
        }

        // V(i) ready (leave K(i+1) pending)
        if (i < 99) { asm volatile("cp.async.wait_group 1;" ::: "memory"); }
        else        { asm volatile("cp.async.wait_group 0;" ::: "memory"); }
        __syncthreads();

        // ---- O += P V : 2-term (Ph*Vh + Ph*Vl) ----
        #pragma unroll
        for (int kb = 0; kb < 4; kb++) {
            uint32_t vf[8][4];
            #pragma unroll
            for (int ct = 0; ct < 8; ct++) {
                uint32_t R  = (uint32_t)(ct*8) + br;
                uint32_t ch = ((uint32_t)(kb*2) + bx) ^ br;
                ldmx4(vf[ct], sb + PVH + bpl + R*128u + ch*16u);
            }
            #pragma unroll
            for (int ct = 0; ct < 8; ct++) mma_bf16(O[ct], ph[kb], &vf[ct][0]);
            #pragma unroll
            for (int ct = 0; ct < 8; ct++) mma_bf16(O[ct], ph[kb], &vf[ct][2]);
        }

        __syncthreads();                       // all warps done reading V
        if (i < 99) {                          // prefetch V(i+1) over next S-GEMM
            ld_plane(sb + PVH, g_v_h + (size_t)b*64*6400 + (i+1)*64, 6400, t);
            ld_plane(sb + PVL, g_v_l + (size_t)b*64*6400 + (i+1)*64, 6400, t);
            asm volatile("cp.async.commit_group;" ::: "memory");
        }
    }

    // ---- normalize: row sums live in quads ----
    lsA += __shfl_xor_sync(0xffffffffu, lsA, 1);
    lsA += __shfl_xor_sync(0xffffffffu, lsA, 2);
    lsB += __shfl_xor_sync(0xffffffffu, lsB, 1);
    lsB += __shfl_xor_sync(0xffffffffu, lsB, 2);
    const float invA = 1.f / lsA;
    const float invB = 1.f / lsB;

    __syncthreads();
    float* stg = (float*)(smem + PKH);      // 64x64 f32 staging = 16KB
    const int gq = lane >> 2, tq = lane & 3;
    #pragma unroll
    for (int ct = 0; ct < 8; ct++) {
        int c = ct*8 + 2*tq;
        stg[(c    )*64 + m0 + gq    ] = O[ct][0] * invA;
        stg[(c + 1)*64 + m0 + gq    ] = O[ct][1] * invA;
        stg[(c    )*64 + m0 + gq + 8] = O[ct][2] * invB;
        stg[(c + 1)*64 + m0 + gq + 8] = O[ct][3] * invB;
    }
    __syncthreads();
    for (int idx = t; idx < 1024; idx += 128) {
        int c = idx >> 4, chn = idx & 15;
        float4 v = *(float4*)&stg[c*64 + chn*4];
        *(float4*)&g_y[((size_t)b*64 + c)*6400 + n0 + chn*4] = v;
    }
}

// ---------------- kernel 3: W-conv + BN statistics ---------------------------
__global__ __launch_bounds__(256) void convW_kernel(
    const float* __restrict__ wW, const float* __restrict__ bW)
{
    __shared__ __align__(16) float ys[64*68];
    __shared__ __align__(16) float ws[64*68];
    __shared__ float ssum[64], ssq[64];
    const int b  = blockIdx.y;
    const int n0 = blockIdx.x * 64;
    const int t  = threadIdx.x;
    const int tx = t & 15, ty = t >> 4;

    const float* yb = g_y + (size_t)b*64*6400;
    for (int i = t; i < 4096; i += 256) {
        int c = i >> 6, n = i & 63;
        ys[c*68 + n] = yb[c*6400 + n0 + n];
    }
    for (int i = t; i < 4096; i += 256) ws[(i & 63)*68 + (i >> 6)] = wW[i];
    if (t < 64) { ssum[t] = 0.f; ssq[t] = 0.f; }
    __syncthreads();

    float acc[4][4];
    #pragma unroll
    for (int j = 0; j < 4; j++) {
        float bb = bW[4*tx + j];
        #pragma unroll
        for (int r = 0; r < 4; r++) acc[r][j] = bb;
    }
    #pragma unroll 4
    for (int c = 0; c < 64; c++) {
        float4 a  = *(const float4*)&ys[c*68 + 4*ty];
        float4 w4 = *(const float4*)&ws[c*68 + 4*tx];
        acc[0][0] += a.x*w4.x; acc[0][1] += a.x*w4.y; acc[0][2] += a.x*w4.z; acc[0][3] += a.x*w4.w;
        acc[1][0] += a.y*w4.x; acc[1][1] += a.y*w4.y; acc[1][2] += a.y*w4.z; acc[1][3] += a.y*w4.w;
        acc[2][0] += a.z*w4.x; acc[2][1] += a.z*w4.y; acc[2][2] += a.z*w4.z; acc[2][3] += a.z*w4.w;
        acc[3][0] += a.w*w4.x; acc[3][1] += a.w*w4.y; acc[3][2] += a.w*w4.z; acc[3][3] += a.w*w4.w;
    }
    float* dst = g_Wy + (size_t)b*64*6400;
    #pragma unroll
    for (int j = 0; j < 4; j++) {
        float4 v = make_float4(acc[0][j], acc[1][j], acc[2][j], acc[3][j]);
        *(float4*)&dst[(4*tx + j)*6400 + n0 + 4*ty] = v;
    }
    #pragma unroll
    for (int j = 0; j < 4; j++) {
        float s = 0.f, q = 0.f;
        #pragma unroll
        for (int r = 0; r < 4; r++) { s += acc[r][j]; q += acc[r][j]*acc[r][j]; }
        atomicAdd(&ssum[4*tx + j], s);
        atomicAdd(&ssq [4*tx + j], q);
    }
    __syncthreads();
    if (t < 64) {
        atomicAdd(&g_stats[t],      ssum[t]);
        atomicAdd(&g_stats[64 + t], ssq[t]);
    }
}

// ---------------- kernel 4: BN scale/shift -----------------------------------
__global__ void bnstats_kernel(const float* __restrict__ gamma,
                               const float* __restrict__ beta)
{
    int c = threadIdx.x;
    const float invN = 1.f / (float)(B_ * N_);
    float mean = g_stats[c] * invN;
    float var  = g_stats[64 + c] * invN - mean*mean;
    float sc   = gamma[c] * rsqrtf(var + 1e-5f);
    g_sc[c]      = sc;
    g_sc[64 + c] = beta[c] - mean*sc;
}

// ---------------- kernel 5: BN apply + residual -------------------------------
__global__ __launch_bounds__(256) void out_kernel(const float* __restrict__ x,
                                                  float* __restrict__ out)
{
    int i   = blockIdx.x * 256 + threadIdx.x;
    int idx = i * 4;
    int c   = (idx / 6400) & 63;
    float4 wy = *(const float4*)&g_Wy[idx];
    float4 xv = *(const float4*)&x[idx];
    float sc = g_sc[c], sh = g_sc[64 + c];
    float4 o;
    o.x = wy.x*sc + sh + xv.x;
    o.y = wy.y*sc + sh + xv.y;
    o.z = wy.z*sc + sh + xv.z;
    o.w = wy.w*sc + sh + xv.w;
    *(float4*)&out[idx] = o;
}

// ---------------- launch -------------------------------------------------------
extern "C" void kernel_launch(void* const* d_in, const int* in_sizes, int n_in,
                              void* d_out, int out_size)
{
    const float* x     = (const float*)d_in[0];
    const float* wt    = (const float*)d_in[1];
    const float* bt    = (const float*)d_in[2];
    const float* wp    = (const float*)d_in[3];
    const float* bp    = (const float*)d_in[4];
    const float* wg    = (const float*)d_in[5];
    const float* bg    = (const float*)d_in[6];
    const float* wW    = (const float*)d_in[7];
    const float* bW    = (const float*)d_in[8];
    const float* gamma = (const float*)d_in[9];
    const float* beta  = (const float*)d_in[10];

    dim3 gproj(100, B_);
    proj3_kernel <<<gproj, 256>>>(x, wt, bt, wp, bp, wg, bg);
    dim3 gflash(100, B_);
    flash_kernel <<<gflash, 128>>>();
    convW_kernel <<<gproj, 256>>>(wW, bW);
    bnstats_kernel<<<1, 64>>>(gamma, beta);
    out_kernel   <<<(B_*C_*N_)/4/256, 256>>>(x, (float*)d_out);
}